// round 6
// baseline (speedup 1.0000x reference)
#include <cuda_runtime.h>

#define IN_CH 64
#define HIDDEN 16
#define OUT_CH 8
#define N_NODES_MAX 50000
#define NTHREADS 256
#define NBLOCKS 296   // 148 SMs x 2 blocks, co-resident by construction

// Scratch (allocation-free rule: __device__ globals)
__device__ float g_deg[N_NODES_MAX];
__device__ float g_p1[N_NODES_MAX * HIDDEN];
__device__ float g_r1[N_NODES_MAX * HIDDEN];
__device__ float g_s1[N_NODES_MAX * HIDDEN];
__device__ float g_p2[N_NODES_MAX * OUT_CH];
__device__ float g_r2[N_NODES_MAX * OUT_CH];
__device__ float g_s2[N_NODES_MAX * OUT_CH];
__device__ int           g_bar_count;   // stays 0 at kernel exit
__device__ volatile int  g_bar_gen;     // monotonically increasing; ok across replays

// Vectorized global reduction (sm_90+): one L2 op for 4 floats.
__device__ __forceinline__ void red_add_v4(float* addr, float4 v) {
    asm volatile("red.global.add.v4.f32 [%0], {%1, %2, %3, %4};"
                 :: "l"(addr), "f"(v.x), "f"(v.y), "f"(v.z), "f"(v.w)
                 : "memory");
}

__device__ __forceinline__ float4 ldcg4(const float* p) {
    float4 v;
    asm volatile("ld.global.cg.v4.f32 {%0,%1,%2,%3}, [%4];"
                 : "=f"(v.x), "=f"(v.y), "=f"(v.z), "=f"(v.w) : "l"(p));
    return v;
}

// Software grid barrier (all NBLOCKS resident by launch_bounds + grid size).
__device__ __forceinline__ void grid_barrier() {
    __syncthreads();
    if (threadIdx.x == 0) {
        int gen = g_bar_gen;
        __threadfence();  // release: make this block's writes visible (also L1 inval)
        if (atomicAdd(&g_bar_count, 1) == NBLOCKS - 1) {
            g_bar_count = 0;
            __threadfence();
            g_bar_gen = gen + 1;
        } else {
            while (g_bar_gen == gen) __nanosleep(64);
        }
        __threadfence();  // acquire side
    }
    __syncthreads();
}

__global__ void __launch_bounds__(NTHREADS, 2)
fused_sage_kernel(const float* __restrict__ x,
                  const float* __restrict__ W1l,
                  const float* __restrict__ W1r,
                  const float* __restrict__ b1,
                  const float* __restrict__ W2l,
                  const float* __restrict__ W2r,
                  const float* __restrict__ b2,
                  const int*   __restrict__ ei,
                  int n_nodes, int n_edges, int n_words,
                  float* __restrict__ out) {
    __shared__ float sW1l[HIDDEN * IN_CH];
    __shared__ float sW1r[HIDDEN * IN_CH];
    __shared__ float sb1[HIDDEN];
    __shared__ float sW2l[OUT_CH * HIDDEN];
    __shared__ float sW2r[OUT_CH * HIDDEN];
    __shared__ float sb2[OUT_CH];
    __shared__ int   s_is64;

    const int T = NBLOCKS * NTHREADS;
    const int t = blockIdx.x * NTHREADS + threadIdx.x;

    for (int i = threadIdx.x; i < HIDDEN * IN_CH; i += NTHREADS) {
        sW1l[i] = W1l[i];
        sW1r[i] = W1r[i];
    }
    for (int i = threadIdx.x; i < OUT_CH * HIDDEN; i += NTHREADS) {
        sW2l[i] = W2l[i];
        sW2r[i] = W2r[i];
    }
    if (threadIdx.x < HIDDEN) sb1[threadIdx.x] = b1[threadIdx.x];
    if (threadIdx.x < OUT_CH) sb2[threadIdx.x] = b2[threadIdx.x];
    if (threadIdx.x == 0) {
        // dtype detect: int64 little-endian indices in [0,50000) -> all odd
        // int32 words zero; int32 -> random indices, never all zero over 512.
        int nz = 0;
        int lim = n_words < 1024 ? n_words : 1024;
        for (int w = 1; w < lim; w += 2) nz += (ei[w] != 0);
        s_is64 = (nz == 0) ? 1 : 0;
    }
    __syncthreads();
    const int is64 = s_is64;

    // ---------------- Phase 1: zero deg/s2 ; gemm1 -> p1, r1 ; zero s1 ----
    for (int i = t; i < n_nodes; i += T) g_deg[i] = 0.0f;
    for (int i = t; i < n_nodes * OUT_CH; i += T) g_s2[i] = 0.0f;

    for (int idx = t; idx < n_nodes * 4; idx += T) {
        int n = idx >> 2;
        int q = idx & 3;
        int h0 = q * 4;
        float accl[4], accr[4];
#pragma unroll
        for (int j = 0; j < 4; j++) { accl[j] = 0.0f; accr[j] = sb1[h0 + j]; }
        const float4* xr = reinterpret_cast<const float4*>(x + (size_t)n * IN_CH);
#pragma unroll
        for (int c4 = 0; c4 < IN_CH / 4; c4++) {
            float4 v = xr[c4];
#pragma unroll
            for (int j = 0; j < 4; j++) {
                const float* wl = &sW1l[(h0 + j) * IN_CH + c4 * 4];
                const float* wr = &sW1r[(h0 + j) * IN_CH + c4 * 4];
                accl[j] += v.x * wl[0] + v.y * wl[1] + v.z * wl[2] + v.w * wl[3];
                accr[j] += v.x * wr[0] + v.y * wr[1] + v.z * wr[2] + v.w * wr[3];
            }
        }
        *reinterpret_cast<float4*>(&g_p1[n * HIDDEN + h0]) =
            make_float4(accl[0], accl[1], accl[2], accl[3]);
        *reinterpret_cast<float4*>(&g_r1[n * HIDDEN + h0]) =
            make_float4(accr[0], accr[1], accr[2], accr[3]);
        *reinterpret_cast<float4*>(&g_s1[n * HIDDEN + h0]) =
            make_float4(0.f, 0.f, 0.f, 0.f);
    }
    grid_barrier();

    // ---------------- Phase 2: scatter1 (2 work items / edge) -------------
    for (int idx = t; idx < n_edges * 2; idx += T) {
        int e = idx >> 1;
        int half = idx & 1;
        int src, dst;
        if (is64) {
            const int2* p = reinterpret_cast<const int2*>(ei);
            src = p[e].x;
            dst = p[n_edges + e].x;
        } else {
            src = ei[e];
            dst = ei[n_edges + e];
        }
        if ((unsigned)src >= (unsigned)n_nodes || (unsigned)dst >= (unsigned)n_nodes) continue;
        if (half == 0) atomicAdd(&g_deg[dst], 1.0f);
        const float4* p = reinterpret_cast<const float4*>(&g_p1[src * HIDDEN + half * 8]);
        float* s = &g_s1[dst * HIDDEN + half * 8];
        red_add_v4(&s[0], p[0]);
        red_add_v4(&s[4], p[1]);
    }
    grid_barrier();

    // ---------------- Phase 3: layer2 (per node) ---------------------------
    for (int n = t; n < n_nodes; n += T) {
        float dv;
        asm volatile("ld.global.cg.f32 %0, [%1];" : "=f"(dv) : "l"(&g_deg[n]));
        float inv_d = 1.0f / fmaxf(dv, 1.0f);
        float h[HIDDEN];
#pragma unroll
        for (int q = 0; q < HIDDEN / 4; q++) {
            float4 sv = ldcg4(&g_s1[n * HIDDEN + q * 4]);
            float4 rv = *reinterpret_cast<const float4*>(&g_r1[n * HIDDEN + q * 4]);
            h[q * 4 + 0] = fmaxf(sv.x * inv_d + rv.x, 0.0f);
            h[q * 4 + 1] = fmaxf(sv.y * inv_d + rv.y, 0.0f);
            h[q * 4 + 2] = fmaxf(sv.z * inv_d + rv.z, 0.0f);
            h[q * 4 + 3] = fmaxf(sv.w * inv_d + rv.w, 0.0f);
        }
        float accl[OUT_CH], accr[OUT_CH];
#pragma unroll
        for (int o = 0; o < OUT_CH; o++) { accl[o] = 0.0f; accr[o] = sb2[o]; }
#pragma unroll
        for (int c = 0; c < HIDDEN; c++) {
            float v = h[c];
#pragma unroll
            for (int o = 0; o < OUT_CH; o++) {
                accl[o] += v * sW2l[o * HIDDEN + c];
                accr[o] += v * sW2r[o * HIDDEN + c];
            }
        }
        float4* p2o = reinterpret_cast<float4*>(&g_p2[n * OUT_CH]);
        float4* r2o = reinterpret_cast<float4*>(&g_r2[n * OUT_CH]);
        p2o[0] = make_float4(accl[0], accl[1], accl[2], accl[3]);
        p2o[1] = make_float4(accl[4], accl[5], accl[6], accl[7]);
        r2o[0] = make_float4(accr[0], accr[1], accr[2], accr[3]);
        r2o[1] = make_float4(accr[4], accr[5], accr[6], accr[7]);
    }
    grid_barrier();

    // ---------------- Phase 4: scatter2 (2 work items / edge) -------------
    for (int idx = t; idx < n_edges * 2; idx += T) {
        int e = idx >> 1;
        int half = idx & 1;
        int src, dst;
        if (is64) {
            const int2* p = reinterpret_cast<const int2*>(ei);
            src = p[e].x;
            dst = p[n_edges + e].x;
        } else {
            src = ei[e];
            dst = ei[n_edges + e];
        }
        if ((unsigned)src >= (unsigned)n_nodes || (unsigned)dst >= (unsigned)n_nodes) continue;
        float4 v = *reinterpret_cast<const float4*>(&g_p2[src * OUT_CH + half * 4]);
        red_add_v4(&g_s2[dst * OUT_CH + half * 4], v);
    }
    grid_barrier();

    // ---------------- Phase 5: combine2 -> out ----------------------------
    for (int idx = t; idx < n_nodes * 2; idx += T) {
        int n = idx >> 1;
        int q = idx & 1;
        float dv;
        asm volatile("ld.global.cg.f32 %0, [%1];" : "=f"(dv) : "l"(&g_deg[n]));
        float inv_d = 1.0f / fmaxf(dv, 1.0f);
        float4 s = ldcg4(&g_s2[n * OUT_CH + q * 4]);
        float4 r = *reinterpret_cast<const float4*>(&g_r2[n * OUT_CH + q * 4]);
        float4 o;
        o.x = s.x * inv_d + r.x;
        o.y = s.y * inv_d + r.y;
        o.z = s.z * inv_d + r.z;
        o.w = s.w * inv_d + r.w;
        *reinterpret_cast<float4*>(&out[n * OUT_CH + q * 4]) = o;
    }
}

extern "C" void kernel_launch(void* const* d_in, const int* in_sizes, int n_in,
                              void* d_out, int out_size) {
    const float* x   = (const float*)d_in[0];
    const float* W1l = (const float*)d_in[1];
    const float* W1r = (const float*)d_in[2];
    const float* b1  = (const float*)d_in[3];
    const float* W2l = (const float*)d_in[4];
    const float* W2r = (const float*)d_in[5];
    const float* b2  = (const float*)d_in[6];
    const int*   ei  = (const int*)d_in[7];

    int n_nodes = in_sizes[0] / IN_CH;
    int n_edges = in_sizes[7] / 2;
    if (n_nodes > N_NODES_MAX) n_nodes = N_NODES_MAX;

    fused_sage_kernel<<<NBLOCKS, NTHREADS>>>(x, W1l, W1r, b1, W2l, W2r, b2, ei,
                                             n_nodes, n_edges, in_sizes[7],
                                             (float*)d_out);
}

// round 7
// speedup vs baseline: 1.0815x; 1.0815x over previous
#include <cuda_runtime.h>

#define IN_CH 64
#define HIDDEN 16
#define OUT_CH 8
#define N_NODES_MAX 50000
#define NTHREADS 256
#define NBLOCKS 444   // 148 SMs x 3 blocks, co-resident via __launch_bounds__(256,3)

// Scratch (allocation-free rule: __device__ globals)
__device__ float g_deg[N_NODES_MAX];
__device__ float g_p1[N_NODES_MAX * HIDDEN];
__device__ float g_r1[N_NODES_MAX * HIDDEN];
__device__ float g_s1[N_NODES_MAX * HIDDEN];
__device__ float g_p2[N_NODES_MAX * OUT_CH];
__device__ float g_r2[N_NODES_MAX * OUT_CH];
__device__ float g_s2[N_NODES_MAX * OUT_CH];
__device__ int           g_bar_count;   // returns to 0 at kernel exit
__device__ volatile int  g_bar_gen;     // monotonically increasing; ok across replays

// Vectorized global reduction (sm_90+): one L2 op for 4 floats.
__device__ __forceinline__ void red_add_v4(float* addr, float4 v) {
    asm volatile("red.global.add.v4.f32 [%0], {%1, %2, %3, %4};"
                 :: "l"(addr), "f"(v.x), "f"(v.y), "f"(v.z), "f"(v.w)
                 : "memory");
}

__device__ __forceinline__ float4 ldcg4(const float* p) {
    float4 v;
    asm volatile("ld.global.cg.v4.f32 {%0,%1,%2,%3}, [%4];"
                 : "=f"(v.x), "=f"(v.y), "=f"(v.z), "=f"(v.w) : "l"(p));
    return v;
}

// Software grid barrier (all NBLOCKS resident by launch_bounds + grid size).
__device__ __forceinline__ void grid_barrier() {
    __syncthreads();
    if (threadIdx.x == 0) {
        int gen = g_bar_gen;
        __threadfence();  // release (gpu scope; also invalidates L1)
        if (atomicAdd(&g_bar_count, 1) == NBLOCKS - 1) {
            g_bar_count = 0;
            __threadfence();
            g_bar_gen = gen + 1;
        } else {
            while (g_bar_gen == gen) __nanosleep(64);
        }
        __threadfence();  // acquire
    }
    __syncthreads();
}

__global__ void __launch_bounds__(NTHREADS, 3)
fused_sage_kernel(const float* __restrict__ x,
                  const float* __restrict__ W1l,
                  const float* __restrict__ W1r,
                  const float* __restrict__ b1,
                  const float* __restrict__ W2l,
                  const float* __restrict__ W2r,
                  const float* __restrict__ b2,
                  const int*   __restrict__ ei,
                  int n_nodes, int n_edges, int n_words,
                  float* __restrict__ out) {
    __shared__ float sW1l[HIDDEN * IN_CH];
    __shared__ float sW1r[HIDDEN * IN_CH];
    __shared__ float sb1[HIDDEN];
    __shared__ float sW2l[OUT_CH * HIDDEN];
    __shared__ float sW2r[OUT_CH * HIDDEN];
    __shared__ float sb2[OUT_CH];

    const int T = NBLOCKS * NTHREADS;
    const int t = blockIdx.x * NTHREADS + threadIdx.x;

    for (int i = threadIdx.x; i < HIDDEN * IN_CH; i += NTHREADS) {
        sW1l[i] = W1l[i];
        sW1r[i] = W1r[i];
    }
    for (int i = threadIdx.x; i < OUT_CH * HIDDEN; i += NTHREADS) {
        sW2l[i] = W2l[i];
        sW2r[i] = W2r[i];
    }
    if (threadIdx.x < HIDDEN) sb1[threadIdx.x] = b1[threadIdx.x];
    if (threadIdx.x < OUT_CH) sb2[threadIdx.x] = b2[threadIdx.x];

    // Parallel dtype detect: int64 little-endian indices in [0,50000) -> all
    // odd int32 words are 0; int32 -> random indices, never all zero over 256.
    int w = 2 * threadIdx.x + 1;
    int mine = (w < n_words) ? (ei[w] != 0) : 0;
    const int is64 = __syncthreads_or(mine) ? 0 : 1;

    // ---------------- Phase 1: zero deg/s2 ; gemm1 -> p1, r1 ; zero s1 ----
    for (int i = t; i < n_nodes; i += T) g_deg[i] = 0.0f;
    for (int i = t; i < n_nodes * OUT_CH; i += T) g_s2[i] = 0.0f;

    for (int idx = t; idx < n_nodes * 4; idx += T) {
        int n = idx >> 2;
        int q = idx & 3;
        int h0 = q * 4;
        float accl[4], accr[4];
#pragma unroll
        for (int j = 0; j < 4; j++) { accl[j] = 0.0f; accr[j] = sb1[h0 + j]; }
        const float4* xr = reinterpret_cast<const float4*>(x + (size_t)n * IN_CH);
#pragma unroll
        for (int c4 = 0; c4 < IN_CH / 4; c4++) {
            float4 v = xr[c4];
#pragma unroll
            for (int j = 0; j < 4; j++) {
                const float* wl = &sW1l[(h0 + j) * IN_CH + c4 * 4];
                const float* wr = &sW1r[(h0 + j) * IN_CH + c4 * 4];
                accl[j] += v.x * wl[0] + v.y * wl[1] + v.z * wl[2] + v.w * wl[3];
                accr[j] += v.x * wr[0] + v.y * wr[1] + v.z * wr[2] + v.w * wr[3];
            }
        }
        *reinterpret_cast<float4*>(&g_p1[n * HIDDEN + h0]) =
            make_float4(accl[0], accl[1], accl[2], accl[3]);
        *reinterpret_cast<float4*>(&g_r1[n * HIDDEN + h0]) =
            make_float4(accr[0], accr[1], accr[2], accr[3]);
        *reinterpret_cast<float4*>(&g_s1[n * HIDDEN + h0]) =
            make_float4(0.f, 0.f, 0.f, 0.f);
    }
    grid_barrier();

    // ---------------- Phase 2: scatter1 (2 work items / edge, MLP via unroll)
    {
        const int total = n_edges * 2;
#pragma unroll 4
        for (int idx = t; idx < total; idx += T) {
            int e = idx >> 1;
            int half = idx & 1;
            int src, dst;
            if (is64) {
                const int2* p = reinterpret_cast<const int2*>(ei);
                src = p[e].x;
                dst = p[n_edges + e].x;
            } else {
                src = ei[e];
                dst = ei[n_edges + e];
            }
            if ((unsigned)src >= (unsigned)n_nodes || (unsigned)dst >= (unsigned)n_nodes) continue;
            if (half == 0) atomicAdd(&g_deg[dst], 1.0f);
            const float4* p = reinterpret_cast<const float4*>(&g_p1[src * HIDDEN + half * 8]);
            float* s = &g_s1[dst * HIDDEN + half * 8];
            red_add_v4(&s[0], p[0]);
            red_add_v4(&s[4], p[1]);
        }
    }
    grid_barrier();

    // ---------------- Phase 3: layer2 (per node) ---------------------------
    for (int n = t; n < n_nodes; n += T) {
        float dv;
        asm volatile("ld.global.cg.f32 %0, [%1];" : "=f"(dv) : "l"(&g_deg[n]));
        float inv_d = 1.0f / fmaxf(dv, 1.0f);
        float h[HIDDEN];
#pragma unroll
        for (int q = 0; q < HIDDEN / 4; q++) {
            float4 sv = ldcg4(&g_s1[n * HIDDEN + q * 4]);
            float4 rv = *reinterpret_cast<const float4*>(&g_r1[n * HIDDEN + q * 4]);
            h[q * 4 + 0] = fmaxf(sv.x * inv_d + rv.x, 0.0f);
            h[q * 4 + 1] = fmaxf(sv.y * inv_d + rv.y, 0.0f);
            h[q * 4 + 2] = fmaxf(sv.z * inv_d + rv.z, 0.0f);
            h[q * 4 + 3] = fmaxf(sv.w * inv_d + rv.w, 0.0f);
        }
        float accl[OUT_CH], accr[OUT_CH];
#pragma unroll
        for (int o = 0; o < OUT_CH; o++) { accl[o] = 0.0f; accr[o] = sb2[o]; }
#pragma unroll
        for (int c = 0; c < HIDDEN; c++) {
            float v = h[c];
#pragma unroll
            for (int o = 0; o < OUT_CH; o++) {
                accl[o] += v * sW2l[o * HIDDEN + c];
                accr[o] += v * sW2r[o * HIDDEN + c];
            }
        }
        float4* p2o = reinterpret_cast<float4*>(&g_p2[n * OUT_CH]);
        float4* r2o = reinterpret_cast<float4*>(&g_r2[n * OUT_CH]);
        p2o[0] = make_float4(accl[0], accl[1], accl[2], accl[3]);
        p2o[1] = make_float4(accl[4], accl[5], accl[6], accl[7]);
        r2o[0] = make_float4(accr[0], accr[1], accr[2], accr[3]);
        r2o[1] = make_float4(accr[4], accr[5], accr[6], accr[7]);
    }
    grid_barrier();

    // ---------------- Phase 4: scatter2 (2 work items / edge, MLP via unroll)
    {
        const int total = n_edges * 2;
#pragma unroll 4
        for (int idx = t; idx < total; idx += T) {
            int e = idx >> 1;
            int half = idx & 1;
            int src, dst;
            if (is64) {
                const int2* p = reinterpret_cast<const int2*>(ei);
                src = p[e].x;
                dst = p[n_edges + e].x;
            } else {
                src = ei[e];
                dst = ei[n_edges + e];
            }
            if ((unsigned)src >= (unsigned)n_nodes || (unsigned)dst >= (unsigned)n_nodes) continue;
            float4 v = *reinterpret_cast<const float4*>(&g_p2[src * OUT_CH + half * 4]);
            red_add_v4(&g_s2[dst * OUT_CH + half * 4], v);
        }
    }
    grid_barrier();

    // ---------------- Phase 5: combine2 -> out ----------------------------
    for (int idx = t; idx < n_nodes * 2; idx += T) {
        int n = idx >> 1;
        int q = idx & 1;
        float dv;
        asm volatile("ld.global.cg.f32 %0, [%1];" : "=f"(dv) : "l"(&g_deg[n]));
        float inv_d = 1.0f / fmaxf(dv, 1.0f);
        float4 s = ldcg4(&g_s2[n * OUT_CH + q * 4]);
        float4 r = *reinterpret_cast<const float4*>(&g_r2[n * OUT_CH + q * 4]);
        float4 o;
        o.x = s.x * inv_d + r.x;
        o.y = s.y * inv_d + r.y;
        o.z = s.z * inv_d + r.z;
        o.w = s.w * inv_d + r.w;
        *reinterpret_cast<float4*>(&out[n * OUT_CH + q * 4]) = o;
    }
}

extern "C" void kernel_launch(void* const* d_in, const int* in_sizes, int n_in,
                              void* d_out, int out_size) {
    const float* x   = (const float*)d_in[0];
    const float* W1l = (const float*)d_in[1];
    const float* W1r = (const float*)d_in[2];
    const float* b1  = (const float*)d_in[3];
    const float* W2l = (const float*)d_in[4];
    const float* W2r = (const float*)d_in[5];
    const float* b2  = (const float*)d_in[6];
    const int*   ei  = (const int*)d_in[7];

    int n_nodes = in_sizes[0] / IN_CH;
    int n_edges = in_sizes[7] / 2;
    if (n_nodes > N_NODES_MAX) n_nodes = N_NODES_MAX;

    fused_sage_kernel<<<NBLOCKS, NTHREADS>>>(x, W1l, W1r, b1, W2l, W2r, b2, ei,
                                             n_nodes, n_edges, in_sizes[7],
                                             (float*)d_out);
}

// round 8
// speedup vs baseline: 1.1149x; 1.0309x over previous
#include <cuda_runtime.h>

#define IN_CH 64
#define HIDDEN 16
#define OUT_CH 8
#define N_NODES_MAX 50000
#define N_EDGES_MAX 800000
#define NTHREADS 256
#define NBLOCKS 592   // 148 SMs x 4 blocks, co-resident via __launch_bounds__(256,4)

// Scratch (allocation-free rule: __device__ globals)
__device__ float g_deg[N_NODES_MAX];
__device__ float g_p1[N_NODES_MAX * HIDDEN];
__device__ float g_r1[N_NODES_MAX * HIDDEN];
__device__ float g_s1[N_NODES_MAX * HIDDEN];
__device__ float g_p2[N_NODES_MAX * OUT_CH];
__device__ float g_r2[N_NODES_MAX * OUT_CH];
__device__ float g_s2[N_NODES_MAX * OUT_CH];
__device__ int2  g_edges[N_EDGES_MAX];       // decoded (src,dst), written in phase 2
__device__ int           g_bar_count;        // returns to 0 at kernel exit
__device__ volatile int  g_bar_gen;          // monotonically increasing; ok across replays

// Vectorized global reduction (sm_90+): one L2 op for 4 floats.
__device__ __forceinline__ void red_add_v4(float* addr, float4 v) {
    asm volatile("red.global.add.v4.f32 [%0], {%1, %2, %3, %4};"
                 :: "l"(addr), "f"(v.x), "f"(v.y), "f"(v.z), "f"(v.w)
                 : "memory");
}

__device__ __forceinline__ float4 ldcg4(const float* p) {
    float4 v;
    asm volatile("ld.global.cg.v4.f32 {%0,%1,%2,%3}, [%4];"
                 : "=f"(v.x), "=f"(v.y), "=f"(v.z), "=f"(v.w) : "l"(p));
    return v;
}

// Software grid barrier (all NBLOCKS resident by launch_bounds + grid size).
__device__ __forceinline__ void grid_barrier() {
    __syncthreads();
    if (threadIdx.x == 0) {
        int gen = g_bar_gen;
        __threadfence();  // release (gpu scope; also invalidates L1)
        if (atomicAdd(&g_bar_count, 1) == NBLOCKS - 1) {
            g_bar_count = 0;
            __threadfence();
            g_bar_gen = gen + 1;
        } else {
            while (g_bar_gen == gen) __nanosleep(64);
        }
        __threadfence();  // acquire
    }
    __syncthreads();
}

__global__ void __launch_bounds__(NTHREADS, 4)
fused_sage_kernel(const float* __restrict__ x,
                  const float* __restrict__ W1l,
                  const float* __restrict__ W1r,
                  const float* __restrict__ b1,
                  const float* __restrict__ W2l,
                  const float* __restrict__ W2r,
                  const float* __restrict__ b2,
                  const int*   __restrict__ ei,
                  int n_nodes, int n_edges, int n_words,
                  float* __restrict__ out) {
    __shared__ float sW1l[HIDDEN * IN_CH];
    __shared__ float sW1r[HIDDEN * IN_CH];
    __shared__ float sb1[HIDDEN];
    __shared__ float sW2l[OUT_CH * HIDDEN];
    __shared__ float sW2r[OUT_CH * HIDDEN];
    __shared__ float sb2[OUT_CH];

    const int T = NBLOCKS * NTHREADS;
    const int t = blockIdx.x * NTHREADS + threadIdx.x;

    for (int i = threadIdx.x; i < HIDDEN * IN_CH; i += NTHREADS) {
        sW1l[i] = W1l[i];
        sW1r[i] = W1r[i];
    }
    for (int i = threadIdx.x; i < OUT_CH * HIDDEN; i += NTHREADS) {
        sW2l[i] = W2l[i];
        sW2r[i] = W2r[i];
    }
    if (threadIdx.x < HIDDEN) sb1[threadIdx.x] = b1[threadIdx.x];
    if (threadIdx.x < OUT_CH) sb2[threadIdx.x] = b2[threadIdx.x];

    // Parallel dtype detect: int64 little-endian indices in [0,50000) -> all
    // odd int32 words are 0; int32 -> random indices, never all zero over 256.
    int w = 2 * threadIdx.x + 1;
    int mine = (w < n_words) ? (ei[w] != 0) : 0;
    const int is64 = __syncthreads_or(mine) ? 0 : 1;

    // ---------------- Phase 1: zero deg/s2 ; gemm1 -> p1, r1 ; zero s1 ----
    for (int i = t; i < n_nodes; i += T) g_deg[i] = 0.0f;
    for (int i = t; i < n_nodes * OUT_CH; i += T) g_s2[i] = 0.0f;

    for (int idx = t; idx < n_nodes * 4; idx += T) {
        int n = idx >> 2;
        int q = idx & 3;
        int h0 = q * 4;
        float accl[4], accr[4];
#pragma unroll
        for (int j = 0; j < 4; j++) { accl[j] = 0.0f; accr[j] = sb1[h0 + j]; }
        const float4* xr = reinterpret_cast<const float4*>(x + (size_t)n * IN_CH);
#pragma unroll
        for (int c4 = 0; c4 < IN_CH / 4; c4++) {
            float4 v = xr[c4];
#pragma unroll
            for (int j = 0; j < 4; j++) {
                const float* wl = &sW1l[(h0 + j) * IN_CH + c4 * 4];
                const float* wr = &sW1r[(h0 + j) * IN_CH + c4 * 4];
                accl[j] += v.x * wl[0] + v.y * wl[1] + v.z * wl[2] + v.w * wl[3];
                accr[j] += v.x * wr[0] + v.y * wr[1] + v.z * wr[2] + v.w * wr[3];
            }
        }
        *reinterpret_cast<float4*>(&g_p1[n * HIDDEN + h0]) =
            make_float4(accl[0], accl[1], accl[2], accl[3]);
        *reinterpret_cast<float4*>(&g_r1[n * HIDDEN + h0]) =
            make_float4(accr[0], accr[1], accr[2], accr[3]);
        *reinterpret_cast<float4*>(&g_s1[n * HIDDEN + h0]) =
            make_float4(0.f, 0.f, 0.f, 0.f);
    }
    grid_barrier();

    // -------- Phase 2: scatter1, 4 threads/edge (quad shares index load) ---
    // Quad lane q handles channels [4q, 4q+4). Lane 0 bumps degree, lane 1
    // stores the decoded edge for phase 4.
    {
        const int total = n_edges * 4;
#pragma unroll 4
        for (int idx = t; idx < total; idx += T) {
            int e = idx >> 2;
            int q = idx & 3;
            int src, dst;
            if (is64) {
                const int2* p = reinterpret_cast<const int2*>(ei);
                src = p[e].x;                 // broadcast within the quad
                dst = p[n_edges + e].x;
            } else {
                src = ei[e];
                dst = ei[n_edges + e];
            }
            if ((unsigned)src >= (unsigned)n_nodes || (unsigned)dst >= (unsigned)n_nodes)
                continue;
            if (q == 0) atomicAdd(&g_deg[dst], 1.0f);
            if (q == 1) g_edges[e] = make_int2(src, dst);
            float4 v = *reinterpret_cast<const float4*>(&g_p1[src * HIDDEN + q * 4]);
            red_add_v4(&g_s1[dst * HIDDEN + q * 4], v);
        }
    }
    grid_barrier();

    // ---------------- Phase 3: layer2 (per node) ---------------------------
    for (int n = t; n < n_nodes; n += T) {
        float dv;
        asm volatile("ld.global.cg.f32 %0, [%1];" : "=f"(dv) : "l"(&g_deg[n]));
        float inv_d = 1.0f / fmaxf(dv, 1.0f);
        float h[HIDDEN];
#pragma unroll
        for (int q = 0; q < HIDDEN / 4; q++) {
            float4 sv = ldcg4(&g_s1[n * HIDDEN + q * 4]);
            float4 rv = *reinterpret_cast<const float4*>(&g_r1[n * HIDDEN + q * 4]);
            h[q * 4 + 0] = fmaxf(sv.x * inv_d + rv.x, 0.0f);
            h[q * 4 + 1] = fmaxf(sv.y * inv_d + rv.y, 0.0f);
            h[q * 4 + 2] = fmaxf(sv.z * inv_d + rv.z, 0.0f);
            h[q * 4 + 3] = fmaxf(sv.w * inv_d + rv.w, 0.0f);
        }
        float accl[OUT_CH], accr[OUT_CH];
#pragma unroll
        for (int o = 0; o < OUT_CH; o++) { accl[o] = 0.0f; accr[o] = sb2[o]; }
#pragma unroll
        for (int c = 0; c < HIDDEN; c++) {
            float v = h[c];
#pragma unroll
            for (int o = 0; o < OUT_CH; o++) {
                accl[o] += v * sW2l[o * HIDDEN + c];
                accr[o] += v * sW2r[o * HIDDEN + c];
            }
        }
        float4* p2o = reinterpret_cast<float4*>(&g_p2[n * OUT_CH]);
        float4* r2o = reinterpret_cast<float4*>(&g_r2[n * OUT_CH]);
        p2o[0] = make_float4(accl[0], accl[1], accl[2], accl[3]);
        p2o[1] = make_float4(accl[4], accl[5], accl[6], accl[7]);
        r2o[0] = make_float4(accr[0], accr[1], accr[2], accr[3]);
        r2o[1] = make_float4(accr[4], accr[5], accr[6], accr[7]);
    }
    grid_barrier();

    // -------- Phase 4: scatter2, 2 threads/edge via decoded edge cache -----
    {
        const int total = n_edges * 2;
#pragma unroll 4
        for (int idx = t; idx < total; idx += T) {
            int e = idx >> 1;
            int half = idx & 1;
            int2 ed = g_edges[e];             // broadcast within the pair
            if ((unsigned)ed.x >= (unsigned)n_nodes || (unsigned)ed.y >= (unsigned)n_nodes)
                continue;
            float4 v = *reinterpret_cast<const float4*>(&g_p2[ed.x * OUT_CH + half * 4]);
            red_add_v4(&g_s2[ed.y * OUT_CH + half * 4], v);
        }
    }
    grid_barrier();

    // ---------------- Phase 5: combine2 -> out ----------------------------
    for (int idx = t; idx < n_nodes * 2; idx += T) {
        int n = idx >> 1;
        int q = idx & 1;
        float dv;
        asm volatile("ld.global.cg.f32 %0, [%1];" : "=f"(dv) : "l"(&g_deg[n]));
        float inv_d = 1.0f / fmaxf(dv, 1.0f);
        float4 s = ldcg4(&g_s2[n * OUT_CH + q * 4]);
        float4 r = *reinterpret_cast<const float4*>(&g_r2[n * OUT_CH + q * 4]);
        float4 o;
        o.x = s.x * inv_d + r.x;
        o.y = s.y * inv_d + r.y;
        o.z = s.z * inv_d + r.z;
        o.w = s.w * inv_d + r.w;
        *reinterpret_cast<float4*>(&out[n * OUT_CH + q * 4]) = o;
    }
}

extern "C" void kernel_launch(void* const* d_in, const int* in_sizes, int n_in,
                              void* d_out, int out_size) {
    const float* x   = (const float*)d_in[0];
    const float* W1l = (const float*)d_in[1];
    const float* W1r = (const float*)d_in[2];
    const float* b1  = (const float*)d_in[3];
    const float* W2l = (const float*)d_in[4];
    const float* W2r = (const float*)d_in[5];
    const float* b2  = (const float*)d_in[6];
    const int*   ei  = (const int*)d_in[7];

    int n_nodes = in_sizes[0] / IN_CH;
    int n_edges = in_sizes[7] / 2;
    if (n_nodes > N_NODES_MAX) n_nodes = N_NODES_MAX;
    if (n_edges > N_EDGES_MAX) n_edges = N_EDGES_MAX;

    fused_sage_kernel<<<NBLOCKS, NTHREADS>>>(x, W1l, W1r, b1, W2l, W2r, b2, ei,
                                             n_nodes, n_edges, in_sizes[7],
                                             (float*)d_out);
}

// round 9
// speedup vs baseline: 1.1228x; 1.0071x over previous
#include <cuda_runtime.h>

#define IN_CH 64
#define HIDDEN 16
#define OUT_CH 8
#define N_NODES_MAX 50000
#define N_EDGES_MAX 800000
#define NTHREADS 256
#define NBLOCKS 592   // 148 SMs x 4 blocks, co-resident via __launch_bounds__(256,4)

// Scratch (allocation-free rule: __device__ globals). +1 dummy sink row.
__device__ float g_deg[N_NODES_MAX + 1];
__device__ float g_p1[(N_NODES_MAX + 1) * HIDDEN];
__device__ float g_r1[N_NODES_MAX * HIDDEN];
__device__ float g_s1[(N_NODES_MAX + 1) * HIDDEN];
__device__ float g_p2[(N_NODES_MAX + 1) * OUT_CH];
__device__ float g_r2[N_NODES_MAX * OUT_CH];
__device__ float g_s2[(N_NODES_MAX + 1) * OUT_CH];
__device__ int2  g_edges[N_EDGES_MAX];       // decoded (src,dst); invalid -> sink
__device__ int           g_bar_count;        // returns to 0 at kernel exit
__device__ volatile int  g_bar_gen;          // monotonically increasing; ok across replays

// Vectorized global reduction (sm_90+): one L2 op for 4 floats.
__device__ __forceinline__ void red_add_v4(float* addr, float4 v) {
    asm volatile("red.global.add.v4.f32 [%0], {%1, %2, %3, %4};"
                 :: "l"(addr), "f"(v.x), "f"(v.y), "f"(v.z), "f"(v.w)
                 : "memory");
}

__device__ __forceinline__ float4 ldcg4(const float* p) {
    float4 v;
    asm volatile("ld.global.cg.v4.f32 {%0,%1,%2,%3}, [%4];"
                 : "=f"(v.x), "=f"(v.y), "=f"(v.z), "=f"(v.w) : "l"(p));
    return v;
}

// Software grid barrier (all NBLOCKS resident by launch_bounds + grid size).
__device__ __forceinline__ void grid_barrier() {
    __syncthreads();
    if (threadIdx.x == 0) {
        int gen = g_bar_gen;
        __threadfence();  // release (gpu scope)
        if (atomicAdd(&g_bar_count, 1) == NBLOCKS - 1) {
            g_bar_count = 0;
            __threadfence();
            g_bar_gen = gen + 1;
        } else {
            while (g_bar_gen == gen) __nanosleep(64);
        }
        __threadfence();  // acquire
    }
    __syncthreads();
}

__global__ void __launch_bounds__(NTHREADS, 4)
fused_sage_kernel(const float* __restrict__ x,
                  const float* __restrict__ W1l,
                  const float* __restrict__ W1r,
                  const float* __restrict__ b1,
                  const float* __restrict__ W2l,
                  const float* __restrict__ W2r,
                  const float* __restrict__ b2,
                  const int*   __restrict__ ei,
                  int n_nodes, int n_edges, int n_words,
                  float* __restrict__ out) {
    __shared__ float sW1l[HIDDEN * IN_CH];
    __shared__ float sW1r[HIDDEN * IN_CH];
    __shared__ float sb1[HIDDEN];
    __shared__ float sW2l[OUT_CH * HIDDEN];
    __shared__ float sW2r[OUT_CH * HIDDEN];
    __shared__ float sb2[OUT_CH];

    const int T = NBLOCKS * NTHREADS;
    const int t = blockIdx.x * NTHREADS + threadIdx.x;

    for (int i = threadIdx.x; i < HIDDEN * IN_CH; i += NTHREADS) {
        sW1l[i] = W1l[i];
        sW1r[i] = W1r[i];
    }
    for (int i = threadIdx.x; i < OUT_CH * HIDDEN; i += NTHREADS) {
        sW2l[i] = W2l[i];
        sW2r[i] = W2r[i];
    }
    if (threadIdx.x < HIDDEN) sb1[threadIdx.x] = b1[threadIdx.x];
    if (threadIdx.x < OUT_CH) sb2[threadIdx.x] = b2[threadIdx.x];

    // Parallel dtype detect: int64 little-endian indices in [0,50000) -> all
    // odd int32 words are 0; int32 -> random indices, never all zero over 256.
    int w = 2 * threadIdx.x + 1;
    int mine = (w < n_words) ? (ei[w] != 0) : 0;
    const int is64 = __syncthreads_or(mine) ? 0 : 1;

    // ---- Phase 0: zero accumulators (deg incl. sink, s1, s2) -------------
    for (int i = t; i < n_nodes + 1; i += T) g_deg[i] = 0.0f;
    for (int i = t; i < (n_nodes + 1) * HIDDEN; i += T) g_s1[i] = 0.0f;
    for (int i = t; i < (n_nodes + 1) * OUT_CH; i += T) g_s2[i] = 0.0f;
    grid_barrier();

    // ---- Phase 1: gemm1 -> p1, r1  ||  decode edges + degree count -------
    for (int idx = t; idx < n_nodes * 4; idx += T) {
        int n = idx >> 2;
        int q = idx & 3;
        int h0 = q * 4;
        float accl[4], accr[4];
#pragma unroll
        for (int j = 0; j < 4; j++) { accl[j] = 0.0f; accr[j] = sb1[h0 + j]; }
        const float4* xr = reinterpret_cast<const float4*>(x + (size_t)n * IN_CH);
#pragma unroll
        for (int c4 = 0; c4 < IN_CH / 4; c4++) {
            float4 v = xr[c4];
#pragma unroll
            for (int j = 0; j < 4; j++) {
                const float* wl = &sW1l[(h0 + j) * IN_CH + c4 * 4];
                const float* wr = &sW1r[(h0 + j) * IN_CH + c4 * 4];
                accl[j] += v.x * wl[0] + v.y * wl[1] + v.z * wl[2] + v.w * wl[3];
                accr[j] += v.x * wr[0] + v.y * wr[1] + v.z * wr[2] + v.w * wr[3];
            }
        }
        *reinterpret_cast<float4*>(&g_p1[n * HIDDEN + h0]) =
            make_float4(accl[0], accl[1], accl[2], accl[3]);
        *reinterpret_cast<float4*>(&g_r1[n * HIDDEN + h0]) =
            make_float4(accr[0], accr[1], accr[2], accr[3]);
    }
    // zero the dummy sink p-rows
    if (t < 4)
        *reinterpret_cast<float4*>(&g_p1[N_NODES_MAX * HIDDEN + t * 4]) =
            make_float4(0.f, 0.f, 0.f, 0.f);
    if (t >= 4 && t < 6)
        *reinterpret_cast<float4*>(&g_p2[N_NODES_MAX * OUT_CH + (t - 4) * 4]) =
            make_float4(0.f, 0.f, 0.f, 0.f);
    // decode edges (independent of gemm1 above)
    for (int e = t; e < n_edges; e += T) {
        int src, dst;
        if (is64) {
            const int2* p = reinterpret_cast<const int2*>(ei);
            src = p[e].x;
            dst = p[n_edges + e].x;
        } else {
            src = ei[e];
            dst = ei[n_edges + e];
        }
        bool ok = ((unsigned)src < (unsigned)n_nodes) & ((unsigned)dst < (unsigned)n_nodes);
        if (!ok) { src = N_NODES_MAX; dst = N_NODES_MAX; }
        g_edges[e] = make_int2(src * HIDDEN, dst * HIDDEN);  // pre-scaled for s1/p1
        if (ok) atomicAdd(&g_deg[dst], 1.0f);
    }
    grid_barrier();

    // ---- Phase 2: scatter1, 4 threads/edge, software-pipelined (U=4) -----
    {
        const int total = n_edges * 4;
        const int q4 = (t & 3) * 4;            // channel offset, invariant
        int idx = t;
        for (; idx + 3 * T < total; idx += 4 * T) {
            int2 ed[4];
#pragma unroll
            for (int u = 0; u < 4; u++) ed[u] = g_edges[(idx + u * T) >> 2];
            float4 v[4];
#pragma unroll
            for (int u = 0; u < 4; u++)
                v[u] = *reinterpret_cast<const float4*>(&g_p1[ed[u].x + q4]);
#pragma unroll
            for (int u = 0; u < 4; u++)
                red_add_v4(&g_s1[ed[u].y + q4], v[u]);
        }
        for (; idx < total; idx += T) {
            int2 ed = g_edges[idx >> 2];
            float4 v = *reinterpret_cast<const float4*>(&g_p1[ed.x + q4]);
            red_add_v4(&g_s1[ed.y + q4], v);
        }
    }
    grid_barrier();

    // ---- Phase 3: layer2 (per node): h=relu(s1/deg + r1); p2,r2 ----------
    for (int n = t; n < n_nodes; n += T) {
        float dv;
        asm volatile("ld.global.cg.f32 %0, [%1];" : "=f"(dv) : "l"(&g_deg[n]));
        float inv_d = 1.0f / fmaxf(dv, 1.0f);
        float h[HIDDEN];
#pragma unroll
        for (int q = 0; q < HIDDEN / 4; q++) {
            float4 sv = ldcg4(&g_s1[n * HIDDEN + q * 4]);
            float4 rv = *reinterpret_cast<const float4*>(&g_r1[n * HIDDEN + q * 4]);
            h[q * 4 + 0] = fmaxf(sv.x * inv_d + rv.x, 0.0f);
            h[q * 4 + 1] = fmaxf(sv.y * inv_d + rv.y, 0.0f);
            h[q * 4 + 2] = fmaxf(sv.z * inv_d + rv.z, 0.0f);
            h[q * 4 + 3] = fmaxf(sv.w * inv_d + rv.w, 0.0f);
        }
        float accl[OUT_CH], accr[OUT_CH];
#pragma unroll
        for (int o = 0; o < OUT_CH; o++) { accl[o] = 0.0f; accr[o] = sb2[o]; }
#pragma unroll
        for (int c = 0; c < HIDDEN; c++) {
            float v = h[c];
#pragma unroll
            for (int o = 0; o < OUT_CH; o++) {
                accl[o] += v * sW2l[o * HIDDEN + c];
                accr[o] += v * sW2r[o * HIDDEN + c];
            }
        }
        float4* p2o = reinterpret_cast<float4*>(&g_p2[n * OUT_CH]);
        float4* r2o = reinterpret_cast<float4*>(&g_r2[n * OUT_CH]);
        p2o[0] = make_float4(accl[0], accl[1], accl[2], accl[3]);
        p2o[1] = make_float4(accl[4], accl[5], accl[6], accl[7]);
        r2o[0] = make_float4(accr[0], accr[1], accr[2], accr[3]);
        r2o[1] = make_float4(accr[4], accr[5], accr[6], accr[7]);
    }
    grid_barrier();

    // ---- Phase 4: scatter2, 2 threads/edge, software-pipelined (U=4) -----
    {
        const int total = n_edges * 2;
        const int q4 = (t & 1) * 4;
        int idx = t;
        for (; idx + 3 * T < total; idx += 4 * T) {
            int2 ed[4];
#pragma unroll
            for (int u = 0; u < 4; u++) ed[u] = g_edges[(idx + u * T) >> 1];
            float4 v[4];
#pragma unroll
            for (int u = 0; u < 4; u++) {
                int srow = (ed[u].x >> 4) * OUT_CH;     // undo HIDDEN scale
                v[u] = *reinterpret_cast<const float4*>(&g_p2[srow + q4]);
            }
#pragma unroll
            for (int u = 0; u < 4; u++) {
                int drow = (ed[u].y >> 4) * OUT_CH;
                red_add_v4(&g_s2[drow + q4], v[u]);
            }
        }
        for (; idx < total; idx += T) {
            int2 ed = g_edges[idx >> 1];
            int srow = (ed.x >> 4) * OUT_CH;
            int drow = (ed.y >> 4) * OUT_CH;
            float4 v = *reinterpret_cast<const float4*>(&g_p2[srow + q4]);
            red_add_v4(&g_s2[drow + q4], v);
        }
    }
    grid_barrier();

    // ---- Phase 5: combine2 -> out -----------------------------------------
    for (int idx = t; idx < n_nodes * 2; idx += T) {
        int n = idx >> 1;
        int q = idx & 1;
        float dv;
        asm volatile("ld.global.cg.f32 %0, [%1];" : "=f"(dv) : "l"(&g_deg[n]));
        float inv_d = 1.0f / fmaxf(dv, 1.0f);
        float4 s = ldcg4(&g_s2[n * OUT_CH + q * 4]);
        float4 r = *reinterpret_cast<const float4*>(&g_r2[n * OUT_CH + q * 4]);
        float4 o;
        o.x = s.x * inv_d + r.x;
        o.y = s.y * inv_d + r.y;
        o.z = s.z * inv_d + r.z;
        o.w = s.w * inv_d + r.w;
        *reinterpret_cast<float4*>(&out[n * OUT_CH + q * 4]) = o;
    }
}

extern "C" void kernel_launch(void* const* d_in, const int* in_sizes, int n_in,
                              void* d_out, int out_size) {
    const float* x   = (const float*)d_in[0];
    const float* W1l = (const float*)d_in[1];
    const float* W1r = (const float*)d_in[2];
    const float* b1  = (const float*)d_in[3];
    const float* W2l = (const float*)d_in[4];
    const float* W2r = (const float*)d_in[5];
    const float* b2  = (const float*)d_in[6];
    const int*   ei  = (const int*)d_in[7];

    int n_nodes = in_sizes[0] / IN_CH;
    int n_edges = in_sizes[7] / 2;
    if (n_nodes > N_NODES_MAX) n_nodes = N_NODES_MAX;
    if (n_edges > N_EDGES_MAX) n_edges = N_EDGES_MAX;

    fused_sage_kernel<<<NBLOCKS, NTHREADS>>>(x, W1l, W1r, b1, W2l, W2r, b2, ei,
                                             n_nodes, n_edges, in_sizes[7],
                                             (float*)d_out);
}